// round 13
// baseline (speedup 1.0000x reference)
#include <cuda_runtime.h>
#include <cuda_fp16.h>
#include <cstdint>
#include <cstddef>

#define B_SZ 16
#define T_SZ 4096
#define D_SZ 512
#define NTOK (B_SZ * T_SZ)     // 65536
#define NTOT 1536              // 3*U
#define KTOT 1024              // halves
#define KW 512                 // K in words (half2)
#define BM 128
#define BN 128
#define BKW 32                 // K-words per chunk (= 64 halves)
#define NCHUNK 16              // 512 / 32
#define NSTAGE 3
#define SA 36                  // smem row stride in words
#define STG_W (2 * BM * SA)    // words per stage (A+B) = 9216
#define DYN_SMEM (NSTAGE * STG_W * 4)    // 110592 B
#define NC 64
#define LC 64

// ---------------- scratch ----------------
__device__ uint32_t g_xh[(size_t)NTOK * 256];    // x as half2 words, k-word-permuted (67 MB)
__device__ uint32_t g_wh[(size_t)NTOT * KW];     // W^T as half2 words, k-word-permuted (3.1 MB)
__device__ float g_act[(size_t)NTOK * NTOT];     // activated z|f|o (402 MB)
__device__ float g_Ac[B_SZ * NC * 512];
__device__ float g_Bc[B_SZ * NC * 512];
__device__ float g_Hs[B_SZ * NC * 512];

// ---------------- helpers ----------------
__device__ __forceinline__ uint32_t smem_u32(const void* p) {
    uint32_t a;
    asm("{ .reg .u64 t; cvta.to.shared.u64 t, %1; cvt.u32.u64 %0, t; }" : "=r"(a) : "l"(p));
    return a;
}
__device__ __forceinline__ float sigm(float v) { return 1.0f / (1.0f + __expf(-v)); }

// pack (lo, hi) floats into one half2 word with RN rounding; lo -> low 16 bits
__device__ __forceinline__ uint32_t pack_h2(float lo, float hi) {
    uint32_t r;
    asm("cvt.rn.f16x2.f32 %0, %1, %2;" : "=r"(r) : "f"(hi), "f"(lo));
    return r;
}

__device__ __forceinline__ void cp16(uint32_t dst, const void* src, uint32_t srcsize) {
    asm volatile("cp.async.cg.shared.global [%0], [%1], 16, %2;"
                 :: "r"(dst), "l"(src), "r"(srcsize) : "memory");
}
__device__ __forceinline__ void cp_commit() {
    asm volatile("cp.async.commit_group;" ::: "memory");
}
__device__ __forceinline__ void cp_wait2() {
    asm volatile("cp.async.wait_group 2;" ::: "memory");
}

__device__ __forceinline__ void mma_f16(float* c, const uint32_t* a, const uint32_t* b) {
    asm volatile(
        "mma.sync.aligned.m16n8k16.row.col.f32.f16.f16.f32 "
        "{%0,%1,%2,%3}, {%4,%5,%6,%7}, {%8,%9}, {%0,%1,%2,%3};"
        : "+f"(c[0]), "+f"(c[1]), "+f"(c[2]), "+f"(c[3])
        : "r"(a[0]), "r"(a[1]), "r"(a[2]), "r"(a[3]), "r"(b[0]), "r"(b[1]));
}

// word-level perm8: logical words (w0..w7) stored in order (w0,w4,w1,w5,w2,w6,w3,w7)
// so an LDS.64 at stored offset 2*t returns the (w_t, w_{t+4}) pair.
__device__ __forceinline__ int permw(int j) {
    int jj = j & 7;
    return (j & ~7) | ((jj < 4) ? (2 * jj) : (2 * (jj - 4) + 1));
}

// ---------------- prep: x -> half2 words, permuted ----------------
__global__ void __launch_bounds__(256) prep_x(const float* __restrict__ x) {
    size_t i = (size_t)blockIdx.x * blockDim.x + threadIdx.x;   // one 16-float group
    size_t fb = i * 16;
    float4 f0 = *(const float4*)(x + fb);
    float4 f1 = *(const float4*)(x + fb + 4);
    float4 f2 = *(const float4*)(x + fb + 8);
    float4 f3 = *(const float4*)(x + fb + 12);
    uint32_t w[8];
    w[0] = pack_h2(f0.x, f0.y);   // w0
    w[1] = pack_h2(f2.x, f2.y);   // w4
    w[2] = pack_h2(f0.z, f0.w);   // w1
    w[3] = pack_h2(f2.z, f2.w);   // w5
    w[4] = pack_h2(f1.x, f1.y);   // w2
    w[5] = pack_h2(f3.x, f3.y);   // w6
    w[6] = pack_h2(f1.z, f1.w);   // w3
    w[7] = pack_h2(f3.z, f3.w);   // w7
    *(uint4*)(g_xh + i * 8)     = make_uint4(w[0], w[1], w[2], w[3]);
    *(uint4*)(g_xh + i * 8 + 4) = make_uint4(w[4], w[5], w[6], w[7]);
}

// ---------------- prep: W[k][u] -> g_wh[n][k-words], permuted ----------------
__global__ void prep_w(
    const float* __restrict__ Wz, const float* __restrict__ Wf, const float* __restrict__ Wo)
{
    __shared__ float tile[32][33];
    int gate = blockIdx.z;
    const float* Wg = (gate == 0) ? Wz : (gate == 1) ? Wf : Wo;
    int kt = blockIdx.x * 32;   // k tile (halves)
    int ut = blockIdx.y * 32;   // u tile
    int lin = threadIdx.y * 16 + threadIdx.x;
    #pragma unroll
    for (int jj = 0; jj < 4; jj++) {
        int kl = (lin >> 5) + jj * 8;
        int ul = lin & 31;
        tile[kl][ul] = Wg[(size_t)(kt + kl) * 512 + ut + ul];
    }
    __syncthreads();
    int tw = threadIdx.x;
    #pragma unroll
    for (int j = 0; j < 2; j++) {
        int ul = threadIdx.y * 2 + j;
        size_t n = (size_t)gate * 512 + ut + ul;
        uint32_t v = pack_h2(tile[2 * tw][ul], tile[2 * tw + 1][ul]);
        g_wh[n * KW + (kt >> 1) + permw(tw)] = v;
    }
}

// ---------------- profiling alignment no-op ----------------
__global__ void noop_k() {}

// ---------------- GEMM + activation ----------------
__device__ __forceinline__ void issue_tile(
    uint32_t* smw, int stage, int kc, int m0, int n0, int tid)
{
    uint32_t* abuf = smw + stage * STG_W;
    uint32_t* bbuf = abuf + BM * SA;
    int w   = (kc < 8) ? 0 : 1;
    int d0w = (kc & 7) * BKW;          // word offset within x row (256 words)
    #pragma unroll
    for (int i = 0; i < 4; i++) {
        int c = tid + i * 256;         // 0..1023
        int row = c >> 3, q = c & 7;   // q*4 word offset
        int m = m0 + row;
        uint32_t ok = !(w == 0 && (m & (T_SZ - 1)) == 0);
        const uint32_t* src = ok ? (g_xh + (size_t)(m - 1 + w) * 256 + d0w + q * 4) : g_xh;
        cp16(smem_u32(abuf + row * SA + q * 4), src, ok ? 16u : 0u);
    }
    int kbw = kc * BKW;
    #pragma unroll
    for (int i = 0; i < 4; i++) {
        int c = tid + i * 256;
        int row = c >> 3, q = c & 7;   // row = n local
        const uint32_t* src = g_wh + (size_t)(n0 + row) * KW + kbw + q * 4;
        cp16(smem_u32(bbuf + row * SA + q * 4), src, 16u);
    }
}

__global__ void __launch_bounds__(256, 2) qrnn_gemm(
    const float* __restrict__ bz, const float* __restrict__ bf, const float* __restrict__ bo)
{
    extern __shared__ uint32_t smw[];
    int tid = threadIdx.x, wid = tid >> 5, lid = tid & 31;
    int g = lid >> 2, tg = lid & 3;
    int n0 = blockIdx.x * BN;
    int m0 = blockIdx.y * BM;
    int gate = n0 >> 9;
    const float* bg = (gate == 0) ? bz : (gate == 1) ? bf : bo;
    int ub = n0 & 511;
    int mwa = (wid >> 2) * 64;   // 2 warp rows, 64 each
    int nwa = (wid & 3) * 32;    // 4 warp cols, 32 each

    float acc[4][4][4];
    #pragma unroll
    for (int mt = 0; mt < 4; mt++)
        #pragma unroll
        for (int nt = 0; nt < 4; nt++)
            #pragma unroll
            for (int r = 0; r < 4; r++) acc[mt][nt][r] = 0.f;

    issue_tile(smw, 0, 0, m0, n0, tid); cp_commit();
    issue_tile(smw, 1, 1, m0, n0, tid); cp_commit();
    issue_tile(smw, 2, 2, m0, n0, tid); cp_commit();

    int stage = 0;
    for (int kc = 0; kc < NCHUNK; kc++) {
        cp_wait2();
        __syncthreads();
        const uint32_t* As = smw + stage * STG_W;
        const uint32_t* Bs = As + BM * SA;
        #pragma unroll
        for (int ks = 0; ks < 4; ks++) {            // 4 k16 groups per chunk
            int ko = ks * 8 + 2 * tg;               // stored pair (w_tg, w_tg+4)
            uint32_t a[4][4], b[4][2];
            #pragma unroll
            for (int mt = 0; mt < 4; mt++) {
                uint2 lo = *(const uint2*)(As + (mwa + mt * 16 + g) * SA + ko);
                uint2 hi = *(const uint2*)(As + (mwa + mt * 16 + g + 8) * SA + ko);
                a[mt][0] = lo.x; a[mt][2] = lo.y;
                a[mt][1] = hi.x; a[mt][3] = hi.y;
            }
            #pragma unroll
            for (int nt = 0; nt < 4; nt++) {
                uint2 v = *(const uint2*)(Bs + (nwa + nt * 8 + g) * SA + ko);
                b[nt][0] = v.x; b[nt][1] = v.y;
            }
            #pragma unroll
            for (int mt = 0; mt < 4; mt++)
                #pragma unroll
                for (int nt = 0; nt < 4; nt++)
                    mma_f16(acc[mt][nt], a[mt], b[nt]);
        }
        __syncthreads();
        if (kc + 3 < NCHUNK) issue_tile(smw, stage, kc + 3, m0, n0, tid);
        cp_commit();
        stage = (stage == NSTAGE - 1) ? 0 : stage + 1;
    }

    // epilogue: bias + activation -> g_act
    #pragma unroll
    for (int mt = 0; mt < 4; mt++) {
        int row = m0 + mwa + mt * 16 + g;
        #pragma unroll
        for (int nt = 0; nt < 4; nt++) {
            int col = nwa + nt * 8 + tg * 2;
            float b0 = bg[ub + col], b1 = bg[ub + col + 1];
            float t0 = acc[mt][nt][0] + b0, t1 = acc[mt][nt][1] + b1;
            float t2 = acc[mt][nt][2] + b0, t3 = acc[mt][nt][3] + b1;
            float2 v0, v1;
            if (gate == 0) { v0.x = tanhf(t0); v0.y = tanhf(t1); v1.x = tanhf(t2); v1.y = tanhf(t3); }
            else           { v0.x = sigm(t0);  v0.y = sigm(t1);  v1.x = sigm(t2);  v1.y = sigm(t3);  }
            *(float2*)(g_act + (size_t)row * NTOT + n0 + col) = v0;
            *(float2*)(g_act + (size_t)(row + 8) * NTOT + n0 + col) = v1;
        }
    }
}

// ---------------- scan ----------------
__global__ void __launch_bounds__(512) scan1() {
    int blk = blockIdx.x;
    int u = threadIdx.x;
    size_t base = (size_t)((blk >> 6) * T_SZ + (blk & 63) * LC) * NTOT;
    float A = 1.f, h = 0.f;
    for (int t = 0; t < LC; t++) {
        float f = g_act[base + (size_t)t * NTOT + 512 + u];
        float z = g_act[base + (size_t)t * NTOT + u];
        h = f * h + (1.f - f) * z;
        A *= f;
    }
    g_Ac[blk * 512 + u] = A;
    g_Bc[blk * 512 + u] = h;
}

__global__ void __launch_bounds__(512) scan2() {
    int b = blockIdx.x, u = threadIdx.x;
    float h = 0.f;
    for (int c = 0; c < NC; c++) {
        int i = (b * NC + c) * 512 + u;
        g_Hs[i] = h;
        h = g_Ac[i] * h + g_Bc[i];
    }
}

__global__ void __launch_bounds__(512) scan3(float* __restrict__ out) {
    int blk = blockIdx.x;
    int u = threadIdx.x;
    size_t base = (size_t)((blk >> 6) * T_SZ + (blk & 63) * LC) * NTOT;
    size_t ob = (size_t)((blk >> 6) * T_SZ + (blk & 63) * LC) * 512;
    float h = g_Hs[blk * 512 + u];
    for (int t = 0; t < LC; t++) {
        float z = g_act[base + (size_t)t * NTOT + u];
        float f = g_act[base + (size_t)t * NTOT + 512 + u];
        float o = g_act[base + (size_t)t * NTOT + 1024 + u];
        h = f * h + (1.f - f) * z;
        out[ob + (size_t)t * 512 + u] = o * h;
    }
}

// ---------------- launch ----------------
extern "C" void kernel_launch(void* const* d_in, const int* in_sizes, int n_in,
                              void* d_out, int out_size) {
    (void)in_sizes; (void)n_in; (void)out_size;
    const float* x  = (const float*)d_in[0];
    const float* Wz = (const float*)d_in[1];
    const float* bz = (const float*)d_in[2];
    const float* Wf = (const float*)d_in[3];
    const float* bf = (const float*)d_in[4];
    const float* Wo = (const float*)d_in[5];
    const float* bo = (const float*)d_in[6];
    float* out = (float*)d_out;

    static bool attr_done = false;
    if (!attr_done) {
        cudaFuncSetAttribute(qrnn_gemm, cudaFuncAttributeMaxDynamicSharedMemorySize, DYN_SMEM);
        attr_done = true;
    }
    prep_x<<<(NTOK * D_SZ / 16 + 255) / 256, 256>>>(x);
    prep_w<<<dim3(KTOT / 32, 512 / 32, 3), dim3(16, 16)>>>(Wz, Wf, Wo);
    noop_k<<<1, 32>>>();   // keeps ncu's captured slot on qrnn_gemm
    dim3 grid(NTOT / BN, NTOK / BM);   // (12, 512)
    qrnn_gemm<<<grid, 256, DYN_SMEM>>>(bz, bf, bo);
    scan1<<<B_SZ * NC, 512>>>();
    scan2<<<B_SZ, 512>>>();
    scan3<<<B_SZ * NC, 512>>>(out);
}

// round 14
// speedup vs baseline: 1.2148x; 1.2148x over previous
#include <cuda_runtime.h>
#include <cuda_fp16.h>
#include <cstdint>
#include <cstddef>

#define B_SZ 16
#define T_SZ 4096
#define D_SZ 512
#define NTOK (B_SZ * T_SZ)     // 65536
#define NTOT 1536              // 3*U
#define KTOT 1024              // halves
#define KW 512                 // K in words (half2)
#define BM 128
#define BN 128
#define BKW 32                 // K-words per chunk (= 64 halves)
#define NCHUNK 16              // 512 / 32
#define NSTAGE 2
#define SA 40                  // smem row stride in words; SA%32==8 -> conflict-free LDS.64 phases
#define STG_W (2 * BM * SA)    // words per stage (A+B) = 10240
#define DYN_SMEM (NSTAGE * STG_W * 4)    // 81920 B
#define NC 64
#define LC 64

// ---------------- scratch ----------------
__device__ uint32_t g_xh[(size_t)NTOK * 256];    // x as half2 words, k-word-permuted (67 MB)
__device__ uint32_t g_wh[(size_t)NTOT * KW];     // W^T as half2 words, k-word-permuted (3.1 MB)
__device__ float g_act[(size_t)NTOK * NTOT];     // activated z|f|o (402 MB)
__device__ float g_Ac[B_SZ * NC * 512];
__device__ float g_Bc[B_SZ * NC * 512];
__device__ float g_Hs[B_SZ * NC * 512];

// ---------------- helpers ----------------
__device__ __forceinline__ uint32_t smem_u32(const void* p) {
    uint32_t a;
    asm("{ .reg .u64 t; cvta.to.shared.u64 t, %1; cvt.u32.u64 %0, t; }" : "=r"(a) : "l"(p));
    return a;
}
__device__ __forceinline__ float sigm(float v) { return 1.0f / (1.0f + __expf(-v)); }

// pack (lo, hi) floats into one half2 word with RN rounding; lo -> low 16 bits
__device__ __forceinline__ uint32_t pack_h2(float lo, float hi) {
    uint32_t r;
    asm("cvt.rn.f16x2.f32 %0, %1, %2;" : "=r"(r) : "f"(hi), "f"(lo));
    return r;
}

__device__ __forceinline__ void cp16(uint32_t dst, const void* src, uint32_t srcsize) {
    asm volatile("cp.async.cg.shared.global [%0], [%1], 16, %2;"
                 :: "r"(dst), "l"(src), "r"(srcsize) : "memory");
}
__device__ __forceinline__ void cp_commit() {
    asm volatile("cp.async.commit_group;" ::: "memory");
}
__device__ __forceinline__ void cp_wait1() {
    asm volatile("cp.async.wait_group 1;" ::: "memory");
}

__device__ __forceinline__ void mma_f16(float* c, const uint32_t* a, const uint32_t* b) {
    asm volatile(
        "mma.sync.aligned.m16n8k16.row.col.f32.f16.f16.f32 "
        "{%0,%1,%2,%3}, {%4,%5,%6,%7}, {%8,%9}, {%0,%1,%2,%3};"
        : "+f"(c[0]), "+f"(c[1]), "+f"(c[2]), "+f"(c[3])
        : "r"(a[0]), "r"(a[1]), "r"(a[2]), "r"(a[3]), "r"(b[0]), "r"(b[1]));
}

// word-level perm8: logical words (w0..w7) stored in order (w0,w4,w1,w5,w2,w6,w3,w7)
// so an LDS.64 at stored offset 2*t returns the (w_t, w_{t+4}) pair.
__device__ __forceinline__ int permw(int j) {
    int jj = j & 7;
    return (j & ~7) | ((jj < 4) ? (2 * jj) : (2 * (jj - 4) + 1));
}

// ---------------- prep: x -> half2 words, permuted ----------------
__global__ void __launch_bounds__(256) prep_x(const float* __restrict__ x) {
    size_t i = (size_t)blockIdx.x * blockDim.x + threadIdx.x;   // one 16-float group
    size_t fb = i * 16;
    float4 f0 = *(const float4*)(x + fb);
    float4 f1 = *(const float4*)(x + fb + 4);
    float4 f2 = *(const float4*)(x + fb + 8);
    float4 f3 = *(const float4*)(x + fb + 12);
    uint32_t w[8];
    w[0] = pack_h2(f0.x, f0.y);   // w0
    w[1] = pack_h2(f2.x, f2.y);   // w4
    w[2] = pack_h2(f0.z, f0.w);   // w1
    w[3] = pack_h2(f2.z, f2.w);   // w5
    w[4] = pack_h2(f1.x, f1.y);   // w2
    w[5] = pack_h2(f3.x, f3.y);   // w6
    w[6] = pack_h2(f1.z, f1.w);   // w3
    w[7] = pack_h2(f3.z, f3.w);   // w7
    *(uint4*)(g_xh + i * 8)     = make_uint4(w[0], w[1], w[2], w[3]);
    *(uint4*)(g_xh + i * 8 + 4) = make_uint4(w[4], w[5], w[6], w[7]);
}

// ---------------- prep: W[k][u] -> g_wh[n][k-words], permuted ----------------
__global__ void prep_w(
    const float* __restrict__ Wz, const float* __restrict__ Wf, const float* __restrict__ Wo)
{
    __shared__ float tile[32][33];
    int gate = blockIdx.z;
    const float* Wg = (gate == 0) ? Wz : (gate == 1) ? Wf : Wo;
    int kt = blockIdx.x * 32;   // k tile (halves)
    int ut = blockIdx.y * 32;   // u tile
    int lin = threadIdx.y * 16 + threadIdx.x;
    #pragma unroll
    for (int jj = 0; jj < 4; jj++) {
        int kl = (lin >> 5) + jj * 8;
        int ul = lin & 31;
        tile[kl][ul] = Wg[(size_t)(kt + kl) * 512 + ut + ul];
    }
    __syncthreads();
    int tw = threadIdx.x;
    #pragma unroll
    for (int j = 0; j < 2; j++) {
        int ul = threadIdx.y * 2 + j;
        size_t n = (size_t)gate * 512 + ut + ul;
        uint32_t v = pack_h2(tile[2 * tw][ul], tile[2 * tw + 1][ul]);
        g_wh[n * KW + (kt >> 1) + permw(tw)] = v;
    }
}

// ---------------- profiling alignment no-op ----------------
__global__ void noop_k() {}

// ---------------- GEMM + activation ----------------
__device__ __forceinline__ void issue_tile(
    uint32_t* smw, int stage, int kc, int m0, int n0, int tid)
{
    uint32_t* abuf = smw + stage * STG_W;
    uint32_t* bbuf = abuf + BM * SA;
    int w   = (kc < 8) ? 0 : 1;
    int d0w = (kc & 7) * BKW;          // word offset within x row (256 words)
    #pragma unroll
    for (int i = 0; i < 4; i++) {
        int c = tid + i * 256;         // 0..1023
        int row = c >> 3, q = c & 7;   // q*4 word offset
        int m = m0 + row;
        uint32_t ok = !(w == 0 && (m & (T_SZ - 1)) == 0);
        const uint32_t* src = ok ? (g_xh + (size_t)(m - 1 + w) * 256 + d0w + q * 4) : g_xh;
        cp16(smem_u32(abuf + row * SA + q * 4), src, ok ? 16u : 0u);
    }
    int kbw = kc * BKW;
    #pragma unroll
    for (int i = 0; i < 4; i++) {
        int c = tid + i * 256;
        int row = c >> 3, q = c & 7;   // row = n local
        const uint32_t* src = g_wh + (size_t)(n0 + row) * KW + kbw + q * 4;
        cp16(smem_u32(bbuf + row * SA + q * 4), src, 16u);
    }
}

__global__ void __launch_bounds__(256, 2) qrnn_gemm(
    const float* __restrict__ bz, const float* __restrict__ bf, const float* __restrict__ bo)
{
    extern __shared__ uint32_t smw[];
    int tid = threadIdx.x, wid = tid >> 5, lid = tid & 31;
    int g = lid >> 2, tg = lid & 3;
    int n0 = blockIdx.x * BN;
    int m0 = blockIdx.y * BM;
    int gate = n0 >> 9;
    const float* bg = (gate == 0) ? bz : (gate == 1) ? bf : bo;
    int ub = n0 & 511;
    int mwa = (wid >> 2) * 64;   // 2 warp rows, 64 each
    int nwa = (wid & 3) * 32;    // 4 warp cols, 32 each

    float acc[4][4][4];
    #pragma unroll
    for (int mt = 0; mt < 4; mt++)
        #pragma unroll
        for (int nt = 0; nt < 4; nt++)
            #pragma unroll
            for (int r = 0; r < 4; r++) acc[mt][nt][r] = 0.f;

    issue_tile(smw, 0, 0, m0, n0, tid); cp_commit();
    issue_tile(smw, 1, 1, m0, n0, tid); cp_commit();

    for (int kc = 0; kc < NCHUNK; kc++) {
        cp_wait1();
        __syncthreads();
        const uint32_t* As = smw + (kc & 1) * STG_W;
        const uint32_t* Bs = As + BM * SA;
        #pragma unroll
        for (int ks = 0; ks < 4; ks++) {            // 4 k16 groups per chunk
            int ko = ks * 8 + 2 * tg;               // stored pair (w_tg, w_tg+4)
            uint32_t a[4][4], b[4][2];
            #pragma unroll
            for (int mt = 0; mt < 4; mt++) {
                uint2 lo = *(const uint2*)(As + (mwa + mt * 16 + g) * SA + ko);
                uint2 hi = *(const uint2*)(As + (mwa + mt * 16 + g + 8) * SA + ko);
                a[mt][0] = lo.x; a[mt][2] = lo.y;
                a[mt][1] = hi.x; a[mt][3] = hi.y;
            }
            #pragma unroll
            for (int nt = 0; nt < 4; nt++) {
                uint2 v = *(const uint2*)(Bs + (nwa + nt * 8 + g) * SA + ko);
                b[nt][0] = v.x; b[nt][1] = v.y;
            }
            #pragma unroll
            for (int mt = 0; mt < 4; mt++)
                #pragma unroll
                for (int nt = 0; nt < 4; nt++)
                    mma_f16(acc[mt][nt], a[mt], b[nt]);
        }
        __syncthreads();
        if (kc + 2 < NCHUNK) issue_tile(smw, kc & 1, kc + 2, m0, n0, tid);
        cp_commit();
    }

    // epilogue: bias + activation -> g_act
    #pragma unroll
    for (int mt = 0; mt < 4; mt++) {
        int row = m0 + mwa + mt * 16 + g;
        #pragma unroll
        for (int nt = 0; nt < 4; nt++) {
            int col = nwa + nt * 8 + tg * 2;
            float b0 = bg[ub + col], b1 = bg[ub + col + 1];
            float t0 = acc[mt][nt][0] + b0, t1 = acc[mt][nt][1] + b1;
            float t2 = acc[mt][nt][2] + b0, t3 = acc[mt][nt][3] + b1;
            float2 v0, v1;
            if (gate == 0) { v0.x = tanhf(t0); v0.y = tanhf(t1); v1.x = tanhf(t2); v1.y = tanhf(t3); }
            else           { v0.x = sigm(t0);  v0.y = sigm(t1);  v1.x = sigm(t2);  v1.y = sigm(t3);  }
            *(float2*)(g_act + (size_t)row * NTOT + n0 + col) = v0;
            *(float2*)(g_act + (size_t)(row + 8) * NTOT + n0 + col) = v1;
        }
    }
}

// ---------------- scan ----------------
__global__ void __launch_bounds__(512) scan1() {
    int blk = blockIdx.x;
    int u = threadIdx.x;
    size_t base = (size_t)((blk >> 6) * T_SZ + (blk & 63) * LC) * NTOT;
    float A = 1.f, h = 0.f;
    for (int t = 0; t < LC; t++) {
        float f = g_act[base + (size_t)t * NTOT + 512 + u];
        float z = g_act[base + (size_t)t * NTOT + u];
        h = f * h + (1.f - f) * z;
        A *= f;
    }
    g_Ac[blk * 512 + u] = A;
    g_Bc[blk * 512 + u] = h;
}

__global__ void __launch_bounds__(512) scan2() {
    int b = blockIdx.x, u = threadIdx.x;
    float h = 0.f;
    for (int c = 0; c < NC; c++) {
        int i = (b * NC + c) * 512 + u;
        g_Hs[i] = h;
        h = g_Ac[i] * h + g_Bc[i];
    }
}

__global__ void __launch_bounds__(512) scan3(float* __restrict__ out) {
    int blk = blockIdx.x;
    int u = threadIdx.x;
    size_t base = (size_t)((blk >> 6) * T_SZ + (blk & 63) * LC) * NTOT;
    size_t ob = (size_t)((blk >> 6) * T_SZ + (blk & 63) * LC) * 512;
    float h = g_Hs[blk * 512 + u];
    for (int t = 0; t < LC; t++) {
        float z = g_act[base + (size_t)t * NTOT + u];
        float f = g_act[base + (size_t)t * NTOT + 512 + u];
        float o = g_act[base + (size_t)t * NTOT + 1024 + u];
        h = f * h + (1.f - f) * z;
        out[ob + (size_t)t * 512 + u] = o * h;
    }
}

// ---------------- launch ----------------
extern "C" void kernel_launch(void* const* d_in, const int* in_sizes, int n_in,
                              void* d_out, int out_size) {
    (void)in_sizes; (void)n_in; (void)out_size;
    const float* x  = (const float*)d_in[0];
    const float* Wz = (const float*)d_in[1];
    const float* bz = (const float*)d_in[2];
    const float* Wf = (const float*)d_in[3];
    const float* bf = (const float*)d_in[4];
    const float* Wo = (const float*)d_in[5];
    const float* bo = (const float*)d_in[6];
    float* out = (float*)d_out;

    static bool attr_done = false;
    if (!attr_done) {
        cudaFuncSetAttribute(qrnn_gemm, cudaFuncAttributeMaxDynamicSharedMemorySize, DYN_SMEM);
        attr_done = true;
    }
    prep_x<<<(NTOK * D_SZ / 16 + 255) / 256, 256>>>(x);
    prep_w<<<dim3(KTOT / 32, 512 / 32, 3), dim3(16, 16)>>>(Wz, Wf, Wo);
    noop_k<<<1, 32>>>();   // keeps ncu's captured slot on qrnn_gemm
    dim3 grid(NTOT / BN, NTOK / BM);   // (12, 512)
    qrnn_gemm<<<grid, 256, DYN_SMEM>>>(bz, bf, bo);
    scan1<<<B_SZ * NC, 512>>>();
    scan2<<<B_SZ, 512>>>();
    scan3<<<B_SZ * NC, 512>>>(out);
}

// round 17
// speedup vs baseline: 1.3601x; 1.1196x over previous
#include <cuda_runtime.h>
#include <cuda_fp16.h>
#include <cstdint>
#include <cstddef>

#define B_SZ 16
#define T_SZ 4096
#define D_SZ 512
#define NTOK (B_SZ * T_SZ)     // 65536
#define NTOT 1536              // 3*U
#define KTOT 1024              // halves
#define KW 512                 // K in words (half2)
#define BM 128
#define BN 128
#define BKW 32                 // K-words per chunk (= 64 halves)
#define NCHUNK 16              // 512 / 32
#define NSTAGE 3
#define ROWW 32                // words per smem row (128 B exactly; XOR swizzle, no pad)
#define STG_W (2 * BM * ROWW)  // words per stage (A+B) = 8192
#define DYN_SMEM (NSTAGE * STG_W * 4)    // 98304 B
#define NC 64
#define LC 64

// ---------------- scratch ----------------
__device__ uint32_t g_xh[(size_t)NTOK * 256];    // x as half2 words, linear (67 MB)
__device__ uint32_t g_wh[(size_t)NTOT * KW];     // W^T as half2 words, linear (3.1 MB)
__device__ float g_act[(size_t)NTOK * NTOT];     // activated z|f|o (402 MB)
__device__ float g_Ac[B_SZ * NC * 512];
__device__ float g_Bc[B_SZ * NC * 512];
__device__ float g_Hs[B_SZ * NC * 512];

// ---------------- helpers ----------------
__device__ __forceinline__ uint32_t smem_u32(const void* p) {
    uint32_t a;
    asm("{ .reg .u64 t; cvta.to.shared.u64 t, %1; cvt.u32.u64 %0, t; }" : "=r"(a) : "l"(p));
    return a;
}
__device__ __forceinline__ float sigm(float v) { return 1.0f / (1.0f + __expf(-v)); }

// pack (lo, hi) floats into one half2 word with RN rounding; lo -> low 16 bits
__device__ __forceinline__ uint32_t pack_h2(float lo, float hi) {
    uint32_t r;
    asm("cvt.rn.f16x2.f32 %0, %1, %2;" : "=r"(r) : "f"(hi), "f"(lo));
    return r;
}

__device__ __forceinline__ void cp16(uint32_t dst, const void* src, uint32_t srcsize) {
    asm volatile("cp.async.cg.shared.global [%0], [%1], 16, %2;"
                 :: "r"(dst), "l"(src), "r"(srcsize) : "memory");
}
__device__ __forceinline__ void cp_commit() {
    asm volatile("cp.async.commit_group;" ::: "memory");
}
__device__ __forceinline__ void cp_wait2() {
    asm volatile("cp.async.wait_group 2;" ::: "memory");
}

__device__ __forceinline__ void mma_f16(float* c, const uint32_t* a, const uint32_t* b) {
    asm volatile(
        "mma.sync.aligned.m16n8k16.row.col.f32.f16.f16.f32 "
        "{%0,%1,%2,%3}, {%4,%5,%6,%7}, {%8,%9}, {%0,%1,%2,%3};"
        : "+f"(c[0]), "+f"(c[1]), "+f"(c[2]), "+f"(c[3])
        : "r"(a[0]), "r"(a[1]), "r"(a[2]), "r"(a[3]), "r"(b[0]), "r"(b[1]));
}

__device__ __forceinline__ void ldsm4(uint32_t* d, uint32_t addr) {
    asm volatile("ldmatrix.sync.aligned.m8n8.x4.shared.b16 {%0,%1,%2,%3}, [%4];"
                 : "=r"(d[0]), "=r"(d[1]), "=r"(d[2]), "=r"(d[3]) : "r"(addr));
}

// ---------------- prep: x -> half2 words (linear) ----------------
__global__ void __launch_bounds__(256) prep_x(const float* __restrict__ x) {
    size_t i = (size_t)blockIdx.x * blockDim.x + threadIdx.x;   // one 16-float group
    size_t fb = i * 16;
    float4 f0 = *(const float4*)(x + fb);
    float4 f1 = *(const float4*)(x + fb + 4);
    float4 f2 = *(const float4*)(x + fb + 8);
    float4 f3 = *(const float4*)(x + fb + 12);
    uint4 o0, o1;
    o0.x = pack_h2(f0.x, f0.y); o0.y = pack_h2(f0.z, f0.w);
    o0.z = pack_h2(f1.x, f1.y); o0.w = pack_h2(f1.z, f1.w);
    o1.x = pack_h2(f2.x, f2.y); o1.y = pack_h2(f2.z, f2.w);
    o1.z = pack_h2(f3.x, f3.y); o1.w = pack_h2(f3.z, f3.w);
    *(uint4*)(g_xh + i * 8)     = o0;
    *(uint4*)(g_xh + i * 8 + 4) = o1;
}

// ---------------- prep: W[k][u] -> g_wh[n][k-words] (linear) ----------------
__global__ void prep_w(
    const float* __restrict__ Wz, const float* __restrict__ Wf, const float* __restrict__ Wo)
{
    __shared__ float tile[32][33];
    int gate = blockIdx.z;
    const float* Wg = (gate == 0) ? Wz : (gate == 1) ? Wf : Wo;
    int kt = blockIdx.x * 32;   // k tile (halves)
    int ut = blockIdx.y * 32;   // u tile
    int lin = threadIdx.y * 16 + threadIdx.x;
    #pragma unroll
    for (int jj = 0; jj < 4; jj++) {
        int kl = (lin >> 5) + jj * 8;
        int ul = lin & 31;
        tile[kl][ul] = Wg[(size_t)(kt + kl) * 512 + ut + ul];
    }
    __syncthreads();
    int tw = threadIdx.x;       // word index 0..15 within 32-half k tile
    #pragma unroll
    for (int j = 0; j < 2; j++) {
        int ul = threadIdx.y * 2 + j;
        size_t n = (size_t)gate * 512 + ut + ul;
        g_wh[n * KW + (kt >> 1) + tw] = pack_h2(tile[2 * tw][ul], tile[2 * tw + 1][ul]);
    }
}

// ---------------- profiling alignment no-op ----------------
__global__ void noop_k() {}

// ---------------- GEMM + activation ----------------
// smem layout per stage: A rows (m 0..127) then B rows (n 0..127); each row 32 words
// (128 B). 16-byte chunk ch of a row is stored at chunk (ch ^ (row & 7)).
__device__ __forceinline__ void issue_tile(
    uint32_t* smw, int stage, int kc, int m0, int n0, int tid)
{
    uint32_t* abuf = smw + stage * STG_W;
    uint32_t* bbuf = abuf + BM * ROWW;
    int w   = (kc < 8) ? 0 : 1;
    int d0w = (kc & 7) * BKW;          // word offset within x row (256 words)
    #pragma unroll
    for (int i = 0; i < 4; i++) {
        int c = tid + i * 256;         // 0..1023
        int row = c >> 3, ch = c & 7;
        int m = m0 + row;
        uint32_t ok = !(w == 0 && (m & (T_SZ - 1)) == 0);
        const uint32_t* src = ok ? (g_xh + (size_t)(m - 1 + w) * 256 + d0w + ch * 4) : g_xh;
        cp16(smem_u32(abuf + row * ROWW + (ch ^ (row & 7)) * 4), src, ok ? 16u : 0u);
    }
    int kbw = kc * BKW;
    #pragma unroll
    for (int i = 0; i < 4; i++) {
        int c = tid + i * 256;
        int row = c >> 3, ch = c & 7;  // row = n local
        const uint32_t* src = g_wh + (size_t)(n0 + row) * KW + kbw + ch * 4;
        cp16(smem_u32(bbuf + row * ROWW + (ch ^ (row & 7)) * 4), src, 16u);
    }
}

__global__ void __launch_bounds__(256, 2) qrnn_gemm(
    const float* __restrict__ bz, const float* __restrict__ bf, const float* __restrict__ bo)
{
    extern __shared__ __align__(128) uint32_t smw[];
    int tid = threadIdx.x, wid = tid >> 5, lid = tid & 31;
    int g = lid >> 2, tg = lid & 3;
    int r7 = lid & 7, j = lid >> 3;    // ldmatrix lane roles
    int n0 = blockIdx.x * BN;
    int m0 = blockIdx.y * BM;
    int gate = n0 >> 9;
    const float* bg = (gate == 0) ? bz : (gate == 1) ? bf : bo;
    int ub = n0 & 511;
    int mwa = (wid >> 2) * 64;   // 2 warp rows, 64 each
    int nwa = (wid & 3) * 32;    // 4 warp cols, 32 each

    uint32_t sbase = smem_u32(smw);
    // ldmatrix base addresses (per stage add stage*STG_W*4)
    // A matrices j: row = mwa + mt*16 + (j&1)*8 + r7, chunk = 2ks + (j>>1)
    uint32_t aoff[4];
    #pragma unroll
    for (int mt = 0; mt < 4; mt++)
        aoff[mt] = (uint32_t)((mwa + mt * 16 + (j & 1) * 8 + r7) * 128 + (r7 << 4));
    // B matrices j: row = nwa + np*16 + (j>>1)*8 + r7, chunk = 2ks + (j&1)
    uint32_t boff[2];
    #pragma unroll
    for (int np = 0; np < 2; np++)
        boff[np] = (uint32_t)(BM * ROWW * 4 + (nwa + np * 16 + (j >> 1) * 8 + r7) * 128 + (r7 << 4));
    uint32_t selA = (uint32_t)((j >> 1) << 4);   // chunk lsb for A
    uint32_t selB = (uint32_t)((j & 1) << 4);    // chunk lsb for B

    float acc[4][4][4];
    #pragma unroll
    for (int mt = 0; mt < 4; mt++)
        #pragma unroll
        for (int nt = 0; nt < 4; nt++)
            #pragma unroll
            for (int rr = 0; rr < 4; rr++) acc[mt][nt][rr] = 0.f;

    issue_tile(smw, 0, 0, m0, n0, tid); cp_commit();
    issue_tile(smw, 1, 1, m0, n0, tid); cp_commit();
    issue_tile(smw, 2, 2, m0, n0, tid); cp_commit();

    int stage = 0;
    for (int kc = 0; kc < NCHUNK; kc++) {
        cp_wait2();
        __syncthreads();
        uint32_t Au = sbase + stage * (STG_W * 4);
        #pragma unroll
        for (int ks = 0; ks < 4; ks++) {
            uint32_t xa = ((uint32_t)(2 * ks) << 4) ^ selA;
            uint32_t xb = ((uint32_t)(2 * ks) << 4) ^ selB;
            uint32_t a[4][4], b[4][2];
            #pragma unroll
            for (int mt = 0; mt < 4; mt++)
                ldsm4(a[mt], (Au + aoff[mt]) ^ xa);
            #pragma unroll
            for (int np = 0; np < 2; np++) {
                uint32_t q[4];
                ldsm4(q, (Au + boff[np]) ^ xb);
                b[2 * np][0] = q[0]; b[2 * np][1] = q[1];
                b[2 * np + 1][0] = q[2]; b[2 * np + 1][1] = q[3];
            }
            #pragma unroll
            for (int mt = 0; mt < 4; mt++)
                #pragma unroll
                for (int nt = 0; nt < 4; nt++)
                    mma_f16(acc[mt][nt], a[mt], b[nt]);
        }
        __syncthreads();
        if (kc + 3 < NCHUNK) issue_tile(smw, stage, kc + 3, m0, n0, tid);
        cp_commit();
        stage = (stage == NSTAGE - 1) ? 0 : stage + 1;
    }

    // epilogue: bias + activation -> g_act
    #pragma unroll
    for (int mt = 0; mt < 4; mt++) {
        int row = m0 + mwa + mt * 16 + g;
        #pragma unroll
        for (int nt = 0; nt < 4; nt++) {
            int col = nwa + nt * 8 + tg * 2;
            float b0 = bg[ub + col], b1 = bg[ub + col + 1];
            float t0 = acc[mt][nt][0] + b0, t1 = acc[mt][nt][1] + b1;
            float t2 = acc[mt][nt][2] + b0, t3 = acc[mt][nt][3] + b1;
            float2 v0, v1;
            if (gate == 0) { v0.x = tanhf(t0); v0.y = tanhf(t1); v1.x = tanhf(t2); v1.y = tanhf(t3); }
            else           { v0.x = sigm(t0);  v0.y = sigm(t1);  v1.x = sigm(t2);  v1.y = sigm(t3);  }
            *(float2*)(g_act + (size_t)row * NTOT + n0 + col) = v0;
            *(float2*)(g_act + (size_t)(row + 8) * NTOT + n0 + col) = v1;
        }
    }
}

// ---------------- scan ----------------
__global__ void __launch_bounds__(512) scan1() {
    int blk = blockIdx.x;
    int u = threadIdx.x;
    size_t base = (size_t)((blk >> 6) * T_SZ + (blk & 63) * LC) * NTOT;
    float A = 1.f, h = 0.f;
    for (int t = 0; t < LC; t++) {
        float f = g_act[base + (size_t)t * NTOT + 512 + u];
        float z = g_act[base + (size_t)t * NTOT + u];
        h = f * h + (1.f - f) * z;
        A *= f;
    }
    g_Ac[blk * 512 + u] = A;
    g_Bc[blk * 512 + u] = h;
}

__global__ void __launch_bounds__(512) scan2() {
    int b = blockIdx.x, u = threadIdx.x;
    float h = 0.f;
    for (int c = 0; c < NC; c++) {
        int i = (b * NC + c) * 512 + u;
        g_Hs[i] = h;
        h = g_Ac[i] * h + g_Bc[i];
    }
}

__global__ void __launch_bounds__(512) scan3(float* __restrict__ out) {
    int blk = blockIdx.x;
    int u = threadIdx.x;
    size_t base = (size_t)((blk >> 6) * T_SZ + (blk & 63) * LC) * NTOT;
    size_t ob = (size_t)((blk >> 6) * T_SZ + (blk & 63) * LC) * 512;
    float h = g_Hs[blk * 512 + u];
    for (int t = 0; t < LC; t++) {
        float z = g_act[base + (size_t)t * NTOT + u];
        float f = g_act[base + (size_t)t * NTOT + 512 + u];
        float o = g_act[base + (size_t)t * NTOT + 1024 + u];
        h = f * h + (1.f - f) * z;
        out[ob + (size_t)t * 512 + u] = o * h;
    }
}

// ---------------- launch ----------------
extern "C" void kernel_launch(void* const* d_in, const int* in_sizes, int n_in,
                              void* d_out, int out_size) {
    (void)in_sizes; (void)n_in; (void)out_size;
    const float* x  = (const float*)d_in[0];
    const float* Wz = (const float*)d_in[1];
    const float* bz = (const float*)d_in[2];
    const float* Wf = (const float*)d_in[3];
    const float* bf = (const float*)d_in[4];
    const float* Wo = (const float*)d_in[5];
    const float* bo = (const float*)d_in[6];
    float* out = (float*)d_out;

    static bool attr_done = false;
    if (!attr_done) {
        cudaFuncSetAttribute(qrnn_gemm, cudaFuncAttributeMaxDynamicSharedMemorySize, DYN_SMEM);
        attr_done = true;
    }
    prep_x<<<(NTOK * D_SZ / 16 + 255) / 256, 256>>>(x);
    prep_w<<<dim3(KTOT / 32, 512 / 32, 3), dim3(16, 16)>>>(Wz, Wf, Wo);
    noop_k<<<1, 32>>>();   // keeps ncu's captured slot on qrnn_gemm
    dim3 grid(NTOT / BN, NTOK / BM);   // (12, 512)
    qrnn_gemm<<<grid, 256, DYN_SMEM>>>(bz, bf, bo);
    scan1<<<B_SZ * NC, 512>>>();
    scan2<<<B_SZ, 512>>>();
    scan3<<<B_SZ * NC, 512>>>(out);
}